// round 4
// baseline (speedup 1.0000x reference)
#include <cuda_runtime.h>

#define NPOS 9
#define NROWS 16384          // T*B
#define D 128
#define TILE_ROWS 64
#define HALF_COLS 64
#define GRID_CTAS 444        // 3 CTAs/SM x 148 SMs -> all co-resident (barrier-safe)
#define BUILD_CTAS 64
#define MAX_ITEMS 1056       // generous bound on 2 * sum(ceil(cnt/64))

__device__ int g_count[NPOS];              // zero at entry; reset on exit
__device__ int g_list[NPOS * NROWS];
__device__ int g_arrive;                   // reset on exit
__device__ int g_exit;                     // reset on exit
__device__ int g_ticket = GRID_CTAS;       // reset to GRID_CTAS on exit

// smem: Ms[128][64] | Xs[128][64] | aux[32] ints
#define SM_FLOATS (D * HALF_COLS * 2)
#define SMEM_BYTES (SM_FLOATS * 4 + 128)

__global__ void __launch_bounds__(256, 3)
fused_transfer(const void* __restrict__ pos_raw,
               const float* __restrict__ x,
               const float* __restrict__ table,
               float* __restrict__ out)
{
    extern __shared__ float smem[];
    float* Ms  = smem;                       // [128][64] this col-half of M
    float* Xs  = smem + D * HALF_COLS;       // [128][64] transposed X tile
    int*   aux = (int*)(smem + SM_FLOATS);   // [0..8]=cnt [9..17]=base [18]=ticket [19..27]=counts

    const int tid = threadIdx.x;
    const int cid = blockIdx.x;

    // ---------------- phase 1: histogram + grouped row lists ----------------
    if (cid < BUILD_CTAS) {
        if (tid < NPOS) aux[tid] = 0;
        // dtype probe (int32 vs int64): words [cid*256, +256) valid either way;
        // int64 => odd words are zero high-words (values 0..15).
        const int* pos32 = (const int*)pos_raw;
        int w = pos32[cid * 256 + tid];
        int is32 = __syncthreads_or((tid & 1) && (w != 0));

        int row = cid * 256 + tid;
        int p = is32 ? pos32[row] : (int)((const long long*)pos_raw)[row];
        int r = (p < 8) ? p : 8;
        int local = atomicAdd(&aux[r], 1);
        __syncthreads();
        if (tid < NPOS) aux[9 + tid] = atomicAdd(&g_count[tid], aux[tid]);
        __syncthreads();
        g_list[r * NROWS + aux[9 + r] + local] = row;
        __threadfence();                     // publish this thread's list write
    }

    // ---------------- device-wide barrier -----------------------------------
    __syncthreads();
    if (tid == 0) {
        atomicAdd(&g_arrive, 1);
        while (*(volatile int*)&g_arrive < GRID_CTAS) { __nanosleep(64); }
        __threadfence();                     // acquire
    }
    __syncthreads();

    // cache group counts in smem
    if (tid < NPOS) aux[19 + tid] = __ldcg(&g_count[tid]);
    __syncthreads();

    const int lane = tid & 31;
    const int wrp  = tid >> 5;
    const int c0   = 2 * lane;

    int item = cid;          // first work item = own cid; then dynamic tickets
    int prev_key = -1;       // (p*2+half) of currently-loaded Ms

    for (;;) {
        // decode item -> (p, chunk, half); uniform across CTA
        int myp = -1, chunk = 0, half = 0, cnt = 0, total = 0;
        #pragma unroll
        for (int i = 0; i < NPOS; i++) {
            int c  = aux[19 + i];
            int it = 2 * ((c + TILE_ROWS - 1) / TILE_ROWS);
            if (item >= total && item < total + it) {
                myp = i; int l = item - total; chunk = l >> 1; half = l & 1; cnt = c;
            }
            total += it;
        }
        if (item >= total) break;

        int row0  = chunk * TILE_ROWS;
        int nrows = cnt - row0; if (nrows > TILE_ROWS) nrows = TILE_ROWS;
        const int* list = g_list + myp * NROWS + row0;

        __syncthreads();   // previous item's readers done before overwriting smem

        // ---- load Ms = table[myp][:, half*64 .. +64) : 2048 float4 ----
        int key = myp * 2 + half;
        if (key != prev_key) {
            prev_key = key;
            const float* Mg = table + myp * D * D + half * HALF_COLS;
            #pragma unroll
            for (int k = 0; k < 8; k++) {
                int i = tid + k * 256;            // 0..2047
                int rM = i >> 4, cM = (i & 15) * 4;
                *(float4*)(Ms + rM * HALF_COLS + cM) =
                    *(const float4*)(Mg + rM * D + cM);
            }
        }

        // ---- gather X rows, transposed into Xs[d][row] ----
        {
            int rl = tid & 63;                    // local row
            int dq = tid >> 6;                    // d-quarter: 32 d values
            int grow = (rl < nrows) ? __ldcg(&list[rl]) : -1;
            const float4* src = (const float4*)(x + (grow < 0 ? 0 : grow) * D + dq * 32);
            #pragma unroll
            for (int k = 0; k < 8; k++) {
                float4 v = (grow >= 0) ? src[k] : make_float4(0.f, 0.f, 0.f, 0.f);
                int d = dq * 32 + k * 4;
                Xs[(d + 0) * 64 + rl] = v.x;      // conflict-free STS.32
                Xs[(d + 1) * 64 + rl] = v.y;
                Xs[(d + 2) * 64 + rl] = v.z;
                Xs[(d + 3) * 64 + rl] = v.w;
            }
        }
        __syncthreads();

        // ---- compute: warp wrp owns rows [8*wrp,+8); lane owns cols c0,c0+1 ----
        const float* Xp = Xs + 8 * wrp;
        const float* Mp = Ms + c0;

        unsigned long long a00 = 0, a01 = 0, a10 = 0, a11 = 0,
                           a20 = 0, a21 = 0, a30 = 0, a31 = 0;

        #pragma unroll 8
        for (int d = 0; d < D; d++) {
            ulonglong2 xa = *(const ulonglong2*)(Xp + d * 64);      // row pairs 0,1
            ulonglong2 xb = *(const ulonglong2*)(Xp + d * 64 + 4);  // row pairs 2,3
            float2 mv = *(const float2*)(Mp + d * 64);
            unsigned long long m0, m1;
            asm("mov.b64 %0, {%1, %1};" : "=l"(m0) : "f"(mv.x));
            asm("mov.b64 %0, {%1, %1};" : "=l"(m1) : "f"(mv.y));
            asm("fma.rn.f32x2 %0, %1, %2, %0;" : "+l"(a00) : "l"(xa.x), "l"(m0));
            asm("fma.rn.f32x2 %0, %1, %2, %0;" : "+l"(a01) : "l"(xa.x), "l"(m1));
            asm("fma.rn.f32x2 %0, %1, %2, %0;" : "+l"(a10) : "l"(xa.y), "l"(m0));
            asm("fma.rn.f32x2 %0, %1, %2, %0;" : "+l"(a11) : "l"(xa.y), "l"(m1));
            asm("fma.rn.f32x2 %0, %1, %2, %0;" : "+l"(a20) : "l"(xb.x), "l"(m0));
            asm("fma.rn.f32x2 %0, %1, %2, %0;" : "+l"(a21) : "l"(xb.x), "l"(m1));
            asm("fma.rn.f32x2 %0, %1, %2, %0;" : "+l"(a30) : "l"(xb.y), "l"(m0));
            asm("fma.rn.f32x2 %0, %1, %2, %0;" : "+l"(a31) : "l"(xb.y), "l"(m1));
        }

        // ---- epilogue: acc pair = (out[r][c], out[r+1][c]) ----
        {
            unsigned long long accs[4][2] = {{a00,a01},{a10,a11},{a20,a21},{a30,a31}};
            #pragma unroll
            for (int rp = 0; rp < 4; rp++) {
                int r = 8 * wrp + 2 * rp;
                float lo0, hi0, lo1, hi1;
                asm("mov.b64 {%0, %1}, %2;" : "=f"(lo0), "=f"(hi0) : "l"(accs[rp][0]));
                asm("mov.b64 {%0, %1}, %2;" : "=f"(lo1), "=f"(hi1) : "l"(accs[rp][1]));
                if (r < nrows) {
                    int grow = __ldcg(&list[r]);
                    *(float2*)(out + grow * D + half * HALF_COLS + c0) =
                        make_float2(lo0, lo1);
                }
                if (r + 1 < nrows) {
                    int grow = __ldcg(&list[r + 1]);
                    *(float2*)(out + grow * D + half * HALF_COLS + c0) =
                        make_float2(hi0, hi1);
                }
            }
        }

        // ---- next ticket ----
        if (tid == 0) aux[18] = atomicAdd(&g_ticket, 1);
        __syncthreads();
        item = aux[18];
    }

    // ---------------- exit: last CTA resets globals for next replay ---------
    __syncthreads();
    if (tid == 0) {
        int e = atomicAdd(&g_exit, 1);
        if (e == GRID_CTAS - 1) {
            #pragma unroll
            for (int i = 0; i < NPOS; i++) g_count[i] = 0;
            g_arrive = 0;
            g_ticket = GRID_CTAS;
            g_exit = 0;
            __threadfence();
        }
    }
}

// ---------------------------------------------------------------------------
extern "C" void kernel_launch(void* const* d_in, const int* in_sizes, int n_in,
                              void* d_out, int out_size) {
    const void*  positions = d_in[0];                 // int32/int64 [T,B] auto-detected
    const float* outputs   = (const float*)d_in[1];   // f32 [T,B,128]
    const float* table     = (const float*)d_in[2];   // f32 [9,128,128]
    float*       out       = (float*)d_out;           // f32 [T,B,128]
    (void)in_sizes; (void)n_in; (void)out_size;

    static cudaError_t attr_once = cudaFuncSetAttribute(
        fused_transfer, cudaFuncAttributeMaxDynamicSharedMemorySize, SMEM_BYTES);
    (void)attr_once;

    fused_transfer<<<GRID_CTAS, 256, SMEM_BYTES>>>(positions, outputs, table, out);
}

// round 6
// speedup vs baseline: 1.4901x; 1.4901x over previous
#include <cuda_runtime.h>
#include <cuda_bf16.h>
#include <cstdint>

#define NPOS 9
#define NROWS 16384          // T*B
#define D 128
#define TILE_M 128
#define GRID_CTAS 148        // 1 CTA/SM, wave-1 co-resident -> device barrier safe
#define BUILD_CTAS 64

__device__ int g_count[NPOS];        // zero at entry; last CTA resets
__device__ int g_list[NPOS * NROWS];
__device__ int g_arrive;
__device__ int g_exit;

// smem map (bytes): fragment-packed operands, one 32KB region per split
#define OFF_BHI 0
#define OFF_BLO 32768
#define OFF_AHI 65536
#define OFF_ALO 98304
#define OFF_AUX 131072
#define SMEM_BYTES (131072 + 128)

// bf16 hi/lo split of a float pair, packed into b32 (low element in low half)
__device__ __forceinline__ void split2(float x, float y, uint32_t& hi, uint32_t& lo) {
    __nv_bfloat162 h = __floats2bfloat162_rn(x, y);
    float hx = __bfloat162float(h.x), hy = __bfloat162float(h.y);
    __nv_bfloat162 l = __floats2bfloat162_rn(x - hx, y - hy);
    hi = *(uint32_t*)&h;
    lo = *(uint32_t*)&l;
}

#define MMA16816(c0, c1, c2, c3, a0, a1, a2, a3, b0, b1)                      \
    asm volatile(                                                             \
        "mma.sync.aligned.m16n8k16.row.col.f32.bf16.bf16.f32 "                \
        "{%0,%1,%2,%3}, {%4,%5,%6,%7}, {%8,%9}, {%0,%1,%2,%3};"               \
        : "+f"(c0), "+f"(c1), "+f"(c2), "+f"(c3)                              \
        : "r"(a0), "r"(a1), "r"(a2), "r"(a3), "r"(b0), "r"(b1))

__global__ void __launch_bounds__(256, 1)
fused_transfer(const void* __restrict__ pos_raw,
               const float* __restrict__ x,
               const float* __restrict__ table,
               float* __restrict__ out)
{
    extern __shared__ char base[];
    int* aux = (int*)(base + OFF_AUX);

    const int tid  = threadIdx.x;
    const int cid  = blockIdx.x;
    const int wid  = tid >> 5;
    const int lane = tid & 31;
    const int g    = lane >> 2;       // fragment groupID
    const int tig  = lane & 3;        // thread-in-group

    // ---------------- phase 1: histogram + grouped row lists ----------------
    if (cid < BUILD_CTAS) {
        if (tid < NPOS) aux[tid] = 0;
        // dtype probe (int32 vs int64): words [cid*256,+256) valid either way;
        // int64 => odd words are zero high-words (values 0..15).
        const int* pos32 = (const int*)pos_raw;
        int w = pos32[cid * 256 + tid];
        int is32 = __syncthreads_or((tid & 1) && (w != 0));

        int row = cid * 256 + tid;
        int p = is32 ? pos32[row] : (int)((const long long*)pos_raw)[row];
        int r = (p < 8) ? p : 8;
        int local = atomicAdd(&aux[r], 1);
        __syncthreads();
        if (tid < NPOS) aux[9 + tid] = atomicAdd(&g_count[tid], aux[tid]);
        __syncthreads();
        g_list[r * NROWS + aux[9 + r] + local] = row;
    }

    // ---------------- device-wide barrier (148 CTAs, 1 wave) -----------------
    __syncthreads();
    if (tid == 0) {
        __threadfence();
        atomicAdd(&g_arrive, 1);
        while (*(volatile int*)&g_arrive < GRID_CTAS) { __nanosleep(64); }
        __threadfence();
    }
    __syncthreads();

    // ---------------- plan: flat item id == cid (items <= 137 <= 148) -------
    int myp = -1, chunk = 0, cnt = 0, total = 0;
    #pragma unroll
    for (int i = 0; i < NPOS; i++) {
        int c = __ldcg(&g_count[i]);
        int it = (c + TILE_M - 1) / TILE_M;
        if (cid >= total && cid < total + it) { myp = i; chunk = cid - total; cnt = c; }
        total += it;
    }

    if (myp >= 0) {
        int row0  = chunk * TILE_M;
        int nrows = cnt - row0;
        if (nrows > TILE_M) nrows = TILE_M;
        const int* list = g_list + myp * NROWS + row0;
        const float* Mg = table + myp * D * D;

        // ---- B convert: m[k][e] -> fragment-packed bf16 hi/lo ----
        // slot(qn=q*16+nb, lane, reg) at byte qn*256 + lane*8 + reg*4
        // reg0 = (m[k0][e], m[k0+1][e]), reg1 = (m[k0+8][e], m[k0+9][e]),
        // k0 = 16q + 2*tig, e = nb*8 + g
        {
            #pragma unroll 4
            for (int it = 0; it < 16; it++) {
                int qn = wid + it * 8;          // 0..127
                int q  = qn >> 4, nb = qn & 15;
                int e  = nb * 8 + g;
                int k0 = 16 * q + 2 * tig;
                float v0 = Mg[(k0    ) * D + e];
                float v1 = Mg[(k0 + 1) * D + e];
                float v2 = Mg[(k0 + 8) * D + e];
                float v3 = Mg[(k0 + 9) * D + e];
                uint32_t h0, l0, h1, l1;
                split2(v0, v1, h0, l0);
                split2(v2, v3, h1, l1);
                uint32_t off = qn * 256 + lane * 8;
                *(uint32_t*)(base + OFF_BHI + off)     = h0;
                *(uint32_t*)(base + OFF_BHI + off + 4) = h1;
                *(uint32_t*)(base + OFF_BLO + off)     = l0;
                *(uint32_t*)(base + OFF_BLO + off + 4) = l1;
            }
        }

        // ---- A gather: x rows -> fragment-packed bf16 hi/lo ----
        // slot(w,q,lane,reg) at byte (w*8+q)*512 + lane*16 + reg*4
        // row r = 16w + (up*8 + gg): reg up+0 = k(2tig,2tig+1), reg up+2 = k(+8,+9)
        {
            int rA = tid >> 1;                  // tile-local row
            int kh = tid & 1;                   // k half: q in [4kh, 4kh+4)
            int grow = (rA < nrows) ? __ldcg(&list[rA]) : -1;
            int aw = rA >> 4, rr = rA & 15, gg = rr & 7, up = rr >> 3;
            #pragma unroll
            for (int qq = 0; qq < 4; qq++) {
                int q = kh * 4 + qq;
                float4 f0, f1, f2, f3;
                if (grow >= 0) {
                    const float4* src = (const float4*)(x + grow * D + q * 16);
                    f0 = src[0]; f1 = src[1]; f2 = src[2]; f3 = src[3];
                } else {
                    f0 = f1 = f2 = f3 = make_float4(0.f, 0.f, 0.f, 0.f);
                }
                float kv[16] = {f0.x, f0.y, f0.z, f0.w, f1.x, f1.y, f1.z, f1.w,
                                f2.x, f2.y, f2.z, f2.w, f3.x, f3.y, f3.z, f3.w};
                #pragma unroll
                for (int t = 0; t < 4; t++) {
                    uint32_t hL, lL, hH, lH;
                    split2(kv[2 * t], kv[2 * t + 1], hL, lL);
                    split2(kv[2 * t + 8], kv[2 * t + 9], hH, lH);
                    uint32_t off = (aw * 8 + q) * 512 + (gg * 4 + t) * 16 + up * 4;
                    *(uint32_t*)(base + OFF_AHI + off)     = hL;   // reg up
                    *(uint32_t*)(base + OFF_AHI + off + 8) = hH;   // reg up+2
                    *(uint32_t*)(base + OFF_ALO + off)     = lL;
                    *(uint32_t*)(base + OFF_ALO + off + 8) = lH;
                }
            }
        }
        __syncthreads();

        // ---- mainloop: per warp 16 rows x 128 cols, K=128, 3-way split ----
        float acc[16][4];
        #pragma unroll
        for (int nb = 0; nb < 16; nb++)
            #pragma unroll
            for (int r = 0; r < 4; r++) acc[nb][r] = 0.f;

        #pragma unroll
        for (int q = 0; q < 8; q++) {
            uint32_t abase = (wid * 8 + q) * 512 + lane * 16;
            uint4 AH = *(const uint4*)(base + OFF_AHI + abase);
            uint4 AL = *(const uint4*)(base + OFF_ALO + abase);
            #pragma unroll
            for (int nb = 0; nb < 16; nb++) {
                uint32_t bbase = (q * 16 + nb) * 256 + lane * 8;
                uint2 BH = *(const uint2*)(base + OFF_BHI + bbase);
                uint2 BL = *(const uint2*)(base + OFF_BLO + bbase);
                MMA16816(acc[nb][0], acc[nb][1], acc[nb][2], acc[nb][3],
                         AH.x, AH.y, AH.z, AH.w, BH.x, BH.y);
                MMA16816(acc[nb][0], acc[nb][1], acc[nb][2], acc[nb][3],
                         AH.x, AH.y, AH.z, AH.w, BL.x, BL.y);
                MMA16816(acc[nb][0], acc[nb][1], acc[nb][2], acc[nb][3],
                         AL.x, AL.y, AL.z, AL.w, BH.x, BH.y);
            }
        }

        // ---- epilogue: c0,c1 -> row g; c2,c3 -> row g+8; cols nb*8+2tig ----
        {
            int r0 = wid * 16 + g;
            int r1 = r0 + 8;
            int grow0 = (r0 < nrows) ? __ldcg(&list[r0]) : -1;
            int grow1 = (r1 < nrows) ? __ldcg(&list[r1]) : -1;
            #pragma unroll
            for (int nb = 0; nb < 16; nb++) {
                int col = nb * 8 + 2 * tig;
                if (grow0 >= 0)
                    *(float2*)(out + grow0 * D + col) = make_float2(acc[nb][0], acc[nb][1]);
                if (grow1 >= 0)
                    *(float2*)(out + grow1 * D + col) = make_float2(acc[nb][2], acc[nb][3]);
            }
        }
    }

    // ---------------- exit: last CTA resets globals for next replay ---------
    __syncthreads();
    if (tid == 0) {
        int e = atomicAdd(&g_exit, 1);
        if (e == GRID_CTAS - 1) {
            #pragma unroll
            for (int i = 0; i < NPOS; i++) g_count[i] = 0;
            g_arrive = 0;
            g_exit = 0;
            __threadfence();
        }
    }
}

// ---------------------------------------------------------------------------
extern "C" void kernel_launch(void* const* d_in, const int* in_sizes, int n_in,
                              void* d_out, int out_size) {
    const void*  positions = d_in[0];                 // int32/int64 [T,B] auto-detected
    const float* outputs   = (const float*)d_in[1];   // f32 [T,B,128]
    const float* table     = (const float*)d_in[2];   // f32 [9,128,128]
    float*       out       = (float*)d_out;           // f32 [T,B,128]
    (void)in_sizes; (void)n_in; (void)out_size;

    static cudaError_t attr_once = cudaFuncSetAttribute(
        fused_transfer, cudaFuncAttributeMaxDynamicSharedMemorySize, SMEM_BYTES);
    (void)attr_once;

    fused_transfer<<<GRID_CTAS, 256, SMEM_BYTES>>>(positions, outputs, table, out);
}